// round 3
// baseline (speedup 1.0000x reference)
#include <cuda_runtime.h>

// Problem constants
#define NUM_EMB   1024
#define DIM       64
#define N_TOKENS  65536
#define BM        128         // tokens per block
#define PAD       68          // smem row pitch in floats (16B-aligned rows for LDS.128)
#define NCHUNK    16          // 1024 codes / 64 per chunk

// Output layout (single fp32 buffer, tuple order flattened)
#define OFF_Q     1
#define OFF_PPL   (1 + N_TOKENS*DIM)
#define OFF_IDX   (2 + N_TOKENS*DIM)

typedef unsigned long long ull;

__device__ float    g_counts[NUM_EMB];   // zero-init; reset by last block each launch
__device__ float    g_loss_sum;
__device__ unsigned g_ticket;

// ---------------------------------------------------------------------------
#define FMA2(acc, a, b) asm("fma.rn.f32x2 %0, %1, %2, %0;" : "+l"(acc) : "l"(a), "l"(b))

// dynamic smem layout (byte offsets)
#define SM_AS    0                         // As: 128*68 floats  = 34816 B
#define SM_BS    34816                     // Bs: 2*64*68 floats = 34816 B
#define SM_ENP   (SM_BS + 34816)           // 69632: 256 partials = 1024 B
#define SM_EN    (SM_ENP + 1024)           // 70656: 64 floats    = 256 B
#define SM_XSQ   (SM_EN + 256)             // 70912: 128 floats   = 512 B
#define SM_REDS  (SM_XSQ + 512)            // 71424: 128*16 f     = 8192 B
#define SM_REDI  (SM_REDS + 8192)          // 79616: 128*16 i     = 8192 B
#define SM_IDX   (SM_REDI + 8192)          // 87808: 128 ints     = 512 B
#define SM_PART  (SM_IDX + 512)            // 88320: 256 floats   = 1024 B
#define SM_TOTAL (SM_PART + 1024)          // 89344 B  (2 CTAs/SM fit)

__device__ __forceinline__ void cp16(unsigned saddr, const void* gaddr) {
    asm volatile("cp.async.ca.shared.global [%0], [%1], 16;" :: "r"(saddr), "l"(gaddr));
}
__device__ __forceinline__ void cp_commit() {
    asm volatile("cp.async.commit_group;" ::: "memory");
}
__device__ __forceinline__ void cp_wait1() {
    asm volatile("cp.async.wait_group 1;" ::: "memory");
}
__device__ __forceinline__ float ldcg(const float* p) {
    float v; asm volatile("ld.global.cg.f32 %0, [%1];" : "=f"(v) : "l"(p)); return v;
}

__global__ __launch_bounds__(256, 2)
void k_main(const float* __restrict__ inputs,
            const float* __restrict__ weight,
            float* __restrict__ out) {
    extern __shared__ char smem_raw[];
    float* As    = (float*)(smem_raw + SM_AS);
    float* Bs    = (float*)(smem_raw + SM_BS);
    float* s_enp = (float*)(smem_raw + SM_ENP);
    float* s_en  = (float*)(smem_raw + SM_EN);
    float* s_xsq = (float*)(smem_raw + SM_XSQ);
    float* red_s = (float*)(smem_raw + SM_REDS);
    int*   red_i = (int*)  (smem_raw + SM_REDI);
    int*   s_idx = (int*)  (smem_raw + SM_IDX);
    float* s_part= (float*)(smem_raw + SM_PART);

    const unsigned bs_addr =
        (unsigned)__cvta_generic_to_shared(smem_raw) + SM_BS;

    const int tid  = threadIdx.x;
    const int tok0 = blockIdx.x * BM;

    // --- prefetch B chunk 0 (cp.async, 16B) ---
    const float4* gW4 = (const float4*)weight;
#pragma unroll
    for (int it = 0; it < 4; ++it) {
        int e = tid + it * 256;                  // 0..1023
        int row = e >> 4, q = e & 15;
        cp16(bs_addr + (unsigned)(row * (PAD*4) + q * 16), gW4 + row * 16 + q);
    }
    cp_commit();

    // --- load token tile As[128][64] (16B granules, coalesced) ---
    {
        const float4* gA4 = (const float4*)(inputs + (size_t)tok0 * DIM);
#pragma unroll
        for (int it = 0; it < 8; ++it) {
            int e = tid + it * 256;              // 0..2047
            int row = e >> 4, q = e & 15;
            ((float4*)(As + row * PAD))[q] = gA4[row * 16 + q];
        }
    }
    __syncthreads();

    // --- ||x||^2 per token: sequential UNFUSED (replicates reference) ---
    if (tid < BM) {
        const float* x = As + tid * PAD;
        float s = 0.f;
#pragma unroll
        for (int d = 0; d < DIM; ++d) {
            float v = x[d];
            s = __fadd_rn(s, __fmul_rn(v, v));
        }
        s_xsq[tid] = s;
    }
    __syncthreads();

    const int tx = tid & 15;   // code lane (16)
    const int ty = tid >> 4;   // token-group lane (16), 8 tokens each

    float xq[8];
#pragma unroll
    for (int i = 0; i < 8; ++i) xq[i] = s_xsq[ty * 8 + i];

    float best[8];
    int   bidx[8];
#pragma unroll
    for (int i = 0; i < 8; ++i) { best[i] = 3.4e38f; bidx[i] = 0x7fffffff; }

    ull acc[32];
#pragma unroll
    for (int a = 0; a < 32; ++a) acc[a] = 0ull;

    const int ecode = tid >> 2;           // ensq: code handled by this thread
    const int equart = tid & 3;           //       which 16-dim quarter

    for (int c = 0; c < NCHUNK; ++c) {
        // prefetch chunk c+1 into the other buffer
        if (c + 1 < NCHUNK) {
            unsigned dst = bs_addr + (unsigned)(((c + 1) & 1) * 64 * PAD * 4);
            const float4* src = gW4 + (size_t)(c + 1) * 1024;
#pragma unroll
            for (int it = 0; it < 4; ++it) {
                int e = tid + it * 256;
                int row = e >> 4, q = e & 15;
                cp16(dst + (unsigned)(row * (PAD*4) + q * 16), src + row * 16 + q);
            }
        }
        cp_commit();
        cp_wait1();            // chunk c's group complete
        __syncthreads();       // ...and visible

        const float* bbuf = Bs + (c & 1) * (64 * PAD);

        // ensq partials for this chunk (sequential unfused within quarter)
        {
            const float* w = bbuf + ecode * PAD + equart * 16;
            float s = 0.f;
#pragma unroll
            for (int d = 0; d < 16; ++d) {
                float v = w[d];
                s = __fadd_rn(s, __fmul_rn(v, v));
            }
            s_enp[tid] = s;
        }

        // --- main FMA loop: 8 tokens x 4 codes, f32x2, LDS.128 ---
        const ulonglong2* a_base = (const ulonglong2*)(As + (ty * 8) * PAD);
        const ulonglong2* b0p = (const ulonglong2*)(bbuf + (tx +  0) * PAD);
        const ulonglong2* b1p = (const ulonglong2*)(bbuf + (tx + 16) * PAD);
        const ulonglong2* b2p = (const ulonglong2*)(bbuf + (tx + 32) * PAD);
        const ulonglong2* b3p = (const ulonglong2*)(bbuf + (tx + 48) * PAD);

#pragma unroll 4
        for (int dd2 = 0; dd2 < 16; ++dd2) {          // 16 x float4 over 64 dims
            ulonglong2 B0 = b0p[dd2];
            ulonglong2 B1 = b1p[dd2];
            ulonglong2 B2 = b2p[dd2];
            ulonglong2 B3 = b3p[dd2];
#pragma unroll
            for (int i = 0; i < 8; ++i) {
                ulonglong2 A = a_base[i * (PAD/4) + dd2];
                FMA2(acc[i*4+0], A.x, B0.x); FMA2(acc[i*4+0], A.y, B0.y);
                FMA2(acc[i*4+1], A.x, B1.x); FMA2(acc[i*4+1], A.y, B1.y);
                FMA2(acc[i*4+2], A.x, B2.x); FMA2(acc[i*4+2], A.y, B2.y);
                FMA2(acc[i*4+3], A.x, B3.x); FMA2(acc[i*4+3], A.y, B3.y);
            }
        }

        __syncthreads();       // partials visible; all Bs reads of buf(c&1) done
        if (tid < 64) {        // combine ensq partials in order
            const float* p = s_enp + tid * 4;
            s_en[tid] = __fadd_rn(__fadd_rn(__fadd_rn(p[0], p[1]), p[2]), p[3]);
        }
        __syncthreads();

        // Epilogue: score = fl(fl(xsq + ensq) - 2*dot), single rounding via FMA
#pragma unroll
        for (int i = 0; i < 8; ++i) {
#pragma unroll
            for (int j = 0; j < 4; ++j) {
                ull v = acc[i * 4 + j];
                acc[i * 4 + j] = 0ull;
                unsigned lo = (unsigned)v, hi = (unsigned)(v >> 32);
                float dot = __fadd_rn(__uint_as_float(lo), __uint_as_float(hi));
                int lidx = tx + j * 16;
                int idx  = c * 64 + lidx;
                float t = __fadd_rn(xq[i], s_en[lidx]);
                float s = fmaf(-2.f, dot, t);
                if (s < best[i] || (s == best[i] && idx < bidx[i])) {
                    best[i] = s; bidx[i] = idx;
                }
            }
        }
    }

    // --- cross-thread argmin per token (tie -> lowest index) ---
#pragma unroll
    for (int i = 0; i < 8; ++i) {
        red_s[(ty * 8 + i) * 16 + tx] = best[i];
        red_i[(ty * 8 + i) * 16 + tx] = bidx[i];
    }
    __syncthreads();

    if (tid < BM) {
        float bs = red_s[tid * 16];
        int   bi = red_i[tid * 16];
#pragma unroll
        for (int x = 1; x < 16; ++x) {
            float s  = red_s[tid * 16 + x];
            int   ix = red_i[tid * 16 + x];
            if (s < bs || (s == bs && ix < bi)) { bs = s; bi = ix; }
        }
        s_idx[tid] = bi;
        out[OFF_IDX + (size_t)(tok0 + tid)] = (float)bi;
        atomicAdd(&g_counts[bi], 1.f);
    }
    __syncthreads();

    // --- gather codes -> quantized output, accumulate squared diff ---
    float local = 0.f;
#pragma unroll
    for (int it = 0; it < 32; ++it) {
        int e = tid + it * 256;              // 0..8191
        int t = e >> 6, d = e & 63;
        float q = weight[(size_t)s_idx[t] * DIM + d];
        float x = As[t * PAD + d];
        out[OFF_Q + (size_t)(tok0 + t) * DIM + d] = q;
        float diff = q - x;
        local = fmaf(diff, diff, local);
    }
    s_part[tid] = local;
    __syncthreads();
    for (int off = 128; off > 0; off >>= 1) {
        if (tid < off) s_part[tid] += s_part[tid + off];
        __syncthreads();
    }
    if (tid == 0) atomicAdd(&g_loss_sum, s_part[0]);

    // --- last-block finalization (ticket pattern) ---
    __shared__ unsigned s_ticket;
    __threadfence();
    if (tid == 0) s_ticket = atomicAdd(&g_ticket, 1u);
    __syncthreads();
    if (s_ticket == (unsigned)(gridDim.x - 1)) {
        // perplexity over 1024 counts (read via L2), then reset state
        float acc_pl = 0.f;
        float cnts[4];
#pragma unroll
        for (int r = 0; r < 4; ++r) {
            float cnt = ldcg(&g_counts[tid + r * 256]);
            cnts[r] = cnt;
            float p = cnt * (1.f / 65536.f);
            acc_pl += p * logf(p + 1e-10f);
        }
        s_part[tid] = acc_pl;
        __syncthreads();
        for (int off = 128; off > 0; off >>= 1) {
            if (tid < off) s_part[tid] += s_part[tid + off];
            __syncthreads();
        }
        if (tid == 0) {
            float ls = ldcg(&g_loss_sum);
            out[0]       = 1.25f * ls * (1.f / (float)(N_TOKENS * DIM));
            out[OFF_PPL] = expf(-s_part[0]);
            g_loss_sum = 0.f;
            g_ticket   = 0u;
        }
        (void)cnts;
#pragma unroll
        for (int r = 0; r < 4; ++r) g_counts[tid + r * 256] = 0.f;
    }
}

// ---------------------------------------------------------------------------
extern "C" void kernel_launch(void* const* d_in, const int* in_sizes, int n_in,
                              void* d_out, int out_size) {
    const float* inputs = (const float*)d_in[0];   // [64,32,32,64] fp32
    const float* weight = (const float*)d_in[1];   // [1024,64] fp32
    float* out = (float*)d_out;

    cudaFuncSetAttribute(k_main, cudaFuncAttributeMaxDynamicSharedMemorySize, SM_TOTAL);
    k_main<<<N_TOKENS / BM, 256, SM_TOTAL>>>(inputs, weight, out);
}

// round 7
// speedup vs baseline: 1.0369x; 1.0369x over previous
#include <cuda_runtime.h>
#include <cuda_bf16.h>
#include <cstdint>

// Problem constants
#define NUM_EMB   1024
#define DIM       64
#define N_TOKENS  65536
#define BM        256          // tokens per CTA
#define BN        128          // codes per chunk
#define NCH       8            // 1024/128
#define PAD       68
#define NTHR      512          // 16 warps

// Output layout (single fp32 buffer)
#define OFF_Q     1
#define OFF_PPL   (1 + N_TOKENS*DIM)
#define OFF_IDX   (2 + N_TOKENS*DIM)

typedef unsigned long long ull;

// Device state
__device__ __nv_bfloat16 g_wsp[NUM_EMB * 128];  // per code: [e1(64) | e2(64)]
__device__ __nv_bfloat16 g_w3 [NUM_EMB * 64];   // per code: e3(64)
__device__ float    g_ensq[NUM_EMB];
__device__ float    g_counts[NUM_EMB];
__device__ float    g_loss_sum;
__device__ unsigned g_ticket;

// ---------------------------------------------------------------------------
// smem layout (bytes)
#define SM_AB     0                        // bf16 [x1|x2]: 256*256 = 65536
#define SM_A3     65536                    // bf16 x3: 256*128 = 32768
#define SM_B      98304                    // 2 bufs * 128*256 = 65536
#define SM_B3     163840                   // 2 bufs * 128*128 = 32768
#define SM_EN     196608                   // 1024 floats = 4096
#define SM_XSQ    200704                   // 256 floats -> 1024
#define SM_IDX    201728                   // 256 ints -> 1024
#define SM_PART   202752                   // 512 floats = 2048
#define SM_TICK   204800
#define SM_TOTAL  204816

// ---------------------------------------------------------------------------
#define LDSM_X4(r0,r1,r2,r3,addr) \
  asm volatile("ldmatrix.sync.aligned.m8n8.x4.shared.b16 {%0,%1,%2,%3}, [%4];" \
    : "=r"(r0),"=r"(r1),"=r"(r2),"=r"(r3) : "r"(addr))

#define MMA16816(d,a,b0,b1) \
  asm volatile("mma.sync.aligned.m16n8k16.row.col.f32.bf16.bf16.f32 " \
    "{%0,%1,%2,%3},{%4,%5,%6,%7},{%8,%9},{%0,%1,%2,%3};" \
    : "+f"((d)[0]),"+f"((d)[1]),"+f"((d)[2]),"+f"((d)[3]) \
    : "r"((a)[0]),"r"((a)[1]),"r"((a)[2]),"r"((a)[3]),"r"(b0),"r"(b1))

__device__ __forceinline__ void cp16(unsigned saddr, const void* gaddr) {
    asm volatile("cp.async.cg.shared.global [%0], [%1], 16;" :: "r"(saddr), "l"(gaddr));
}
#define CP_COMMIT() asm volatile("cp.async.commit_group;" ::: "memory")
#define CP_WAIT1()  asm volatile("cp.async.wait_group 1;" ::: "memory")
#define CP_WAIT0()  asm volatile("cp.async.wait_group 0;" ::: "memory")
__device__ __forceinline__ float ldcg(const float* p) {
    float v; asm volatile("ld.global.cg.f32 %0, [%1];" : "=f"(v) : "l"(p)); return v;
}

// top-3 key insert (smaller key = better (score, idx))
__device__ __forceinline__ void ins3(ull& t0, ull& t1, ull& t2, ull k) {
    if (k < t2) {
        if (k < t0)      { t2 = t1; t1 = t0; t0 = k; }
        else if (k < t1) { t2 = t1; t1 = k; }
        else               t2 = k;
    }
}
__device__ __forceinline__ ull mkkey(float s, int idx) {
    return ((ull)__float_as_uint(s) << 10) | (unsigned)idx;
}
__device__ __forceinline__ float keysc(ull k) {
    return __uint_as_float((unsigned)(k >> 10));
}

// ---------------------------------------------------------------------------
// k_prep: W exact 3-way bf16 split + code norms (sequential unfused = ref)
// ---------------------------------------------------------------------------
__global__ void k_prep(const float* __restrict__ weight) {
    __shared__ float sw[128 * PAD];
    const int tid = threadIdx.x;             // 128
    const int b   = blockIdx.x;              // 8
    const float* g = weight + (size_t)b * 128 * DIM;
#pragma unroll
    for (int i = 0; i < 64; ++i) {
        int e = tid + i * 128;
        sw[(e >> 6) * PAD + (e & 63)] = g[e];
    }
    __syncthreads();
    const int k = b * 128 + tid;
    const float* x = sw + tid * PAD;
    float s = 0.f;
#pragma unroll
    for (int d = 0; d < DIM; ++d) {
        float v = x[d];
        s = __fadd_rn(s, __fmul_rn(v, v));
        __nv_bfloat16 e1 = __float2bfloat16_rn(v);
        float r1 = v - __bfloat162float(e1);
        __nv_bfloat16 e2 = __float2bfloat16_rn(r1);
        float r2 = r1 - __bfloat162float(e2);
        __nv_bfloat16 e3 = __float2bfloat16_rn(r2);
        g_wsp[(size_t)k * 128 + d]      = e1;
        g_wsp[(size_t)k * 128 + 64 + d] = e2;
        g_w3 [(size_t)k * 64 + d]       = e3;
    }
    g_ensq[k] = s;
}

// ---------------------------------------------------------------------------
// k_main: 6-term bf16-split mma.sync GEMM + exact-rescore argmin + epilogue
// ---------------------------------------------------------------------------
__global__ __launch_bounds__(NTHR, 1)
void k_main(const float* __restrict__ inputs,
            const float* __restrict__ weight,
            float* __restrict__ out) {
    extern __shared__ char smem[];
    float* s_en  = (float*)(smem + SM_EN);
    float* s_xsq = (float*)(smem + SM_XSQ);
    int*   s_idx = (int*)  (smem + SM_IDX);
    float* s_part= (float*)(smem + SM_PART);
    unsigned* s_tick = (unsigned*)(smem + SM_TICK);

    const uint32_t sbase = (uint32_t)__cvta_generic_to_shared(smem);
    const int tid  = threadIdx.x;
    const int w    = tid >> 5;
    const int lane = tid & 31;
    const int tok0 = blockIdx.x * BM;

    // --- prefetch B chunk 0: [e1|e2] (256B rows) + e3 (128B rows) ---
#pragma unroll
    for (int it = 0; it < 4; ++it) {
        int e = tid + it * NTHR;             // 0..2047
        int row = e >> 4, g = e & 15;
        uint32_t dst = sbase + SM_B + row * 256 + ((g >> 3) << 7)
                     + ((((g & 7) ^ (row & 7)) << 4));
        cp16(dst, g_wsp + ((size_t)row << 7) + g * 8);
    }
#pragma unroll
    for (int it = 0; it < 2; ++it) {
        int e = tid + it * NTHR;             // 0..1023
        int row = e >> 3, g = e & 7;
        uint32_t dst = sbase + SM_B3 + row * 128 + (((g ^ (row & 7)) << 4));
        cp16(dst, g_w3 + ((size_t)row << 6) + g * 8);
    }
    CP_COMMIT();

#pragma unroll
    for (int it = 0; it < 2; ++it) s_en[tid + it * NTHR] = g_ensq[tid + it * NTHR];

    // --- A exact 3-way bf16 split straight from gmem (coalesced) ---
    {
        const float* gx = inputs + (size_t)tok0 * DIM;
#pragma unroll
        for (int it = 0; it < 32; ++it) {
            int e = tid + it * NTHR;         // 0..16383
            int row = e >> 6, d = e & 63;
            float v = __ldg(gx + e);
            __nv_bfloat16 x1 = __float2bfloat16_rn(v);
            float r1 = v - __bfloat162float(x1);
            __nv_bfloat16 x2 = __float2bfloat16_rn(r1);
            float r2 = r1 - __bfloat162float(x2);
            __nv_bfloat16 x3 = __float2bfloat16_rn(r2);
            uint32_t sw = (uint32_t)((((d >> 3) & 7) ^ (row & 7)) << 4)
                        | (uint32_t)((d * 2) & 15);
            *(__nv_bfloat16*)(smem + SM_AB + row * 256 + sw)       = x1;
            *(__nv_bfloat16*)(smem + SM_AB + row * 256 + 128 + sw) = x2;
            *(__nv_bfloat16*)(smem + SM_A3 + row * 128 + sw)       = x3;
        }
    }

    // --- ||x||^2: sequential UNFUSED (replicates reference rounding) ---
    if (tid < BM) {
        const float* x = inputs + (size_t)(tok0 + tid) * DIM;
        float s = 0.f;
#pragma unroll
        for (int d = 0; d < DIM; ++d) {
            float v = __ldg(x + d);
            s = __fadd_rn(s, __fmul_rn(v, v));
        }
        s_xsq[tid] = s;
    }
    __syncthreads();

    // --- per-warp A fragments in registers ---
    uint32_t afr[8][4];                      // [x1|x2], K=128
    uint32_t afr3[4][4];                     // x3, K=64
    {
        const int tr = lane & 15;
        const int kadd = (lane >> 4) * 16;
#pragma unroll
        for (int u = 0; u < 8; ++u) {
            int kb = u * 32 + kadd;
            uint32_t addr = sbase + SM_AB + (w * 16 + tr) * 256 + (kb & 128)
                          + (((((kb >> 4) & 7) ^ (tr & 7)) << 4));
            LDSM_X4(afr[u][0], afr[u][1], afr[u][2], afr[u][3], addr);
        }
#pragma unroll
        for (int u = 0; u < 4; ++u) {
            int kb = u * 32 + kadd;
            uint32_t addr = sbase + SM_A3 + (w * 16 + tr) * 128
                          + (((((kb >> 4) & 7) ^ (tr & 7)) << 4));
            LDSM_X4(afr3[u][0], afr3[u][1], afr3[u][2], afr3[u][3], addr);
        }
    }

    // --- B lane address offsets ---
    const int cr = lane & 7;
    const int klane = (lane >> 3) & 3;
    uint32_t boff[4];
#pragma unroll
    for (int i = 0; i < 4; ++i) {
        int kb = i * 64 + klane * 16;
        boff[i] = (uint32_t)(cr * 256 + (kb & 128)
                + (((((kb >> 4) & 7) ^ cr) << 4)));
    }
    uint32_t boff3[2];
#pragma unroll
    for (int i = 0; i < 2; ++i)
        boff3[i] = (uint32_t)(cr * 128 + ((((i * 4 + klane) & 7) ^ cr) << 4));

    const float xq_lo = s_xsq[w * 16 + (lane >> 2)];
    const float xq_hi = s_xsq[w * 16 + (lane >> 2) + 8];
    ull kLo0 = ~0ull, kLo1 = ~0ull, kLo2 = ~0ull;
    ull kHi0 = ~0ull, kHi1 = ~0ull, kHi2 = ~0ull;

    for (int c = 0; c < NCH; ++c) {
        if (c + 1 < NCH) {
            const uint32_t dst0  = sbase + SM_B  + ((c + 1) & 1) * 32768;
            const uint32_t dst03 = sbase + SM_B3 + ((c + 1) & 1) * 16384;
            const size_t srow = (size_t)(c + 1) * BN;
#pragma unroll
            for (int it = 0; it < 4; ++it) {
                int e = tid + it * NTHR;
                int row = e >> 4, g = e & 15;
                uint32_t dst = dst0 + row * 256 + ((g >> 3) << 7)
                             + ((((g & 7) ^ (row & 7)) << 4));
                cp16(dst, g_wsp + ((srow + row) << 7) + g * 8);
            }
#pragma unroll
            for (int it = 0; it < 2; ++it) {
                int e = tid + it * NTHR;
                int row = e >> 3, g = e & 7;
                uint32_t dst = dst03 + row * 128 + (((g ^ (row & 7)) << 4));
                cp16(dst, g_w3 + ((srow + row) << 6) + g * 8);
            }
            CP_COMMIT();
            CP_WAIT1();
        } else {
            CP_COMMIT();
            CP_WAIT0();
        }
        __syncthreads();

        const uint32_t bbuf  = sbase + SM_B  + (c & 1) * 32768;
        const uint32_t bbuf3 = sbase + SM_B3 + (c & 1) * 16384;

#pragma unroll 1
        for (int s8 = 0; s8 < 8; ++s8) {
            const int n0a = s8 * 16;
            const int n0b = n0a + 8;
            float dA[4] = {0.f, 0.f, 0.f, 0.f};
            float dB[4] = {0.f, 0.f, 0.f, 0.f};
            uint32_t fa[8], fb[8];

            // ---- phase e1: x1.e1, x2.e1, x3.e1 ----
            LDSM_X4(fa[0],fa[1],fa[2],fa[3], bbuf + n0a * 256 + boff[0]);
            LDSM_X4(fa[4],fa[5],fa[6],fa[7], bbuf + n0a * 256 + boff[1]);
            LDSM_X4(fb[0],fb[1],fb[2],fb[3], bbuf + n0b * 256 + boff[0]);
            LDSM_X4(fb[4],fb[5],fb[6],fb[7], bbuf + n0b * 256 + boff[1]);
#pragma unroll
            for (int j = 0; j < 4; ++j) {
                MMA16816(dA, afr[j],    fa[2*j], fa[2*j+1]);
                MMA16816(dB, afr[j],    fb[2*j], fb[2*j+1]);
            }
#pragma unroll
            for (int j = 0; j < 4; ++j) {
                MMA16816(dA, afr[4+j],  fa[2*j], fa[2*j+1]);
                MMA16816(dB, afr[4+j],  fb[2*j], fb[2*j+1]);
            }
#pragma unroll
            for (int j = 0; j < 4; ++j) {
                MMA16816(dA, afr3[j],   fa[2*j], fa[2*j+1]);
                MMA16816(dB, afr3[j],   fb[2*j], fb[2*j+1]);
            }
            // ---- phase e2: x1.e2, x2.e2 ----
            LDSM_X4(fa[0],fa[1],fa[2],fa[3], bbuf + n0a * 256 + boff[2]);
            LDSM_X4(fa[4],fa[5],fa[6],fa[7], bbuf + n0a * 256 + boff[3]);
            LDSM_X4(fb[0],fb[1],fb[2],fb[3], bbuf + n0b * 256 + boff[2]);
            LDSM_X4(fb[4],fb[5],fb[6],fb[7], bbuf + n0b * 256 + boff[3]);
#pragma unroll
            for (int j = 0; j < 4; ++j) {
                MMA16816(dA, afr[j],    fa[2*j], fa[2*j+1]);
                MMA16816(dB, afr[j],    fb[2*j], fb[2*j+1]);
            }
#pragma unroll
            for (int j = 0; j < 4; ++j) {
                MMA16816(dA, afr[4+j],  fa[2*j], fa[2*j+1]);
                MMA16816(dB, afr[4+j],  fb[2*j], fb[2*j+1]);
            }
            // ---- phase e3: x1.e3 ----
            LDSM_X4(fa[0],fa[1],fa[2],fa[3], bbuf3 + n0a * 128 + boff3[0]);
            LDSM_X4(fa[4],fa[5],fa[6],fa[7], bbuf3 + n0a * 128 + boff3[1]);
            LDSM_X4(fb[0],fb[1],fb[2],fb[3], bbuf3 + n0b * 128 + boff3[0]);
            LDSM_X4(fb[4],fb[5],fb[6],fb[7], bbuf3 + n0b * 128 + boff3[1]);
#pragma unroll
            for (int j = 0; j < 4; ++j) {
                MMA16816(dA, afr[j],    fa[2*j], fa[2*j+1]);
                MMA16816(dB, afr[j],    fb[2*j], fb[2*j+1]);
            }

            // approx score = fl(fl(xsq + ensq) - 2*dot); track top-3 keys
            {
                int col = c * BN + n0a + (lane & 3) * 2;
                float en0 = s_en[col], en1 = s_en[col + 1];
                ins3(kLo0,kLo1,kLo2, mkkey(fmaf(-2.f, dA[0], __fadd_rn(xq_lo, en0)), col));
                ins3(kLo0,kLo1,kLo2, mkkey(fmaf(-2.f, dA[1], __fadd_rn(xq_lo, en1)), col + 1));
                ins3(kHi0,kHi1,kHi2, mkkey(fmaf(-2.f, dA[2], __fadd_rn(xq_hi, en0)), col));
                ins3(kHi0,kHi1,kHi2, mkkey(fmaf(-2.f, dA[3], __fadd_rn(xq_hi, en1)), col + 1));
            }
            {
                int col = c * BN + n0b + (lane & 3) * 2;
                float en0 = s_en[col], en1 = s_en[col + 1];
                ins3(kLo0,kLo1,kLo2, mkkey(fmaf(-2.f, dB[0], __fadd_rn(xq_lo, en0)), col));
                ins3(kLo0,kLo1,kLo2, mkkey(fmaf(-2.f, dB[1], __fadd_rn(xq_lo, en1)), col + 1));
                ins3(kHi0,kHi1,kHi2, mkkey(fmaf(-2.f, dB[2], __fadd_rn(xq_hi, en0)), col));
                ins3(kHi0,kHi1,kHi2, mkkey(fmaf(-2.f, dB[3], __fadd_rn(xq_hi, en1)), col + 1));
            }
        }
        __syncthreads();
    }

    // --- winner resolution: window filter + exact (round-1) rescore ---
#pragma unroll
    for (int half = 0; half < 2; ++half) {
        ull k0 = half ? kHi0 : kLo0;
        ull k1 = half ? kHi1 : kLo1;
        ull k2 = half ? kHi2 : kLo2;
        float xq = half ? xq_hi : xq_lo;
        int trow = w * 16 + (lane >> 2) + half * 8;

        ull m = k0, o;
        o = __shfl_xor_sync(0xffffffffu, m, 1); m = o < m ? o : m;
        o = __shfl_xor_sync(0xffffffffu, m, 2); m = o < m ? o : m;
        float win = keysc(m) + 1e-5f;

        float s0f = keysc(k0), s1f = keysc(k1), s2f = keysc(k2);
        int cnt = (int)(s0f <= win) + (int)(s1f <= win) + (int)(s2f <= win);
        cnt += __shfl_xor_sync(0xffffffffu, cnt, 1);
        cnt += __shfl_xor_sync(0xffffffffu, cnt, 2);

        ull ebest = ~0ull;
        if (cnt > 1) {
            const float* xrow = inputs + (size_t)(tok0 + trow) * DIM;
            ull   ks[3] = {k0, k1, k2};
            float sf[3] = {s0f, s1f, s2f};
#pragma unroll 1
            for (int j = 0; j < 3; ++j) {
                if (sf[j] <= win) {
                    int idx = (int)(ks[j] & 1023);
                    const float* wrow = weight + (size_t)idx * DIM;
                    float aLo = 0.f, aHi = 0.f;
#pragma unroll
                    for (int d = 0; d < 32; ++d) {
                        aLo = fmaf(__ldg(xrow + 2*d),     __ldg(wrow + 2*d),     aLo);
                        aHi = fmaf(__ldg(xrow + 2*d + 1), __ldg(wrow + 2*d + 1), aHi);
                    }
                    float dot = __fadd_rn(aLo, aHi);
                    float es = fmaf(-2.f, dot, __fadd_rn(xq, s_en[idx]));
                    ull ek = mkkey(es, idx);
                    if (ek < ebest) ebest = ek;
                }
            }
        }
        o = __shfl_xor_sync(0xffffffffu, ebest, 1); ebest = o < ebest ? o : ebest;
        o = __shfl_xor_sync(0xffffffffu, ebest, 2); ebest = o < ebest ? o : ebest;

        int widx = (cnt == 1) ? (int)(m & 1023) : (int)(ebest & 1023);
        if ((lane & 3) == 0) {
            s_idx[trow] = widx;
            out[OFF_IDX + (size_t)(tok0 + trow)] = (float)widx;
            atomicAdd(&g_counts[widx], 1.f);
        }
    }
    __syncthreads();

    // --- gather codes -> quantized output + loss partial ---
    float local = 0.f;
    {
        const float* gx = inputs + (size_t)tok0 * DIM;
#pragma unroll
        for (int it = 0; it < 32; ++it) {
            int e = tid + it * NTHR;         // 0..16383
            int t = e >> 6, d = e & 63;
            float q = weight[(size_t)s_idx[t] * DIM + d];
            float x = __ldg(gx + e);
            out[OFF_Q + (size_t)(tok0 + t) * DIM + d] = q;
            float diff = q - x;
            local = fmaf(diff, diff, local);
        }
    }
    s_part[tid] = local;
    __syncthreads();
    for (int off = 256; off > 0; off >>= 1) {
        if (tid < off) s_part[tid] += s_part[tid + off];
        __syncthreads();
    }
    if (tid == 0) atomicAdd(&g_loss_sum, s_part[0]);

    // --- last-block finalization (ticket) ---
    __threadfence();
    if (tid == 0) *s_tick = atomicAdd(&g_ticket, 1u);
    __syncthreads();
    if (*s_tick == (unsigned)(gridDim.x - 1)) {
        float acc_pl = 0.f;
#pragma unroll
        for (int rj = 0; rj < 2; ++rj) {
            float cnt = ldcg(&g_counts[tid + rj * NTHR]);
            float p = cnt * (1.f / 65536.f);
            acc_pl += p * logf(p + 1e-10f);
        }
        s_part[tid] = acc_pl;
        __syncthreads();
        for (int off = 256; off > 0; off >>= 1) {
            if (tid < off) s_part[tid] += s_part[tid + off];
            __syncthreads();
        }
        if (tid == 0) {
            float ls = ldcg(&g_loss_sum);
            out[0]       = 1.25f * ls * (1.f / (float)(N_TOKENS * DIM));
            out[OFF_PPL] = expf(-s_part[0]);
            g_loss_sum = 0.f;
            g_ticket   = 0u;
        }
#pragma unroll
        for (int rj = 0; rj < 2; ++rj) g_counts[tid + rj * NTHR] = 0.f;
    }
}

// ---------------------------------------------------------------------------
extern "C" void kernel_launch(void* const* d_in, const int* in_sizes, int n_in,
                              void* d_out, int out_size) {
    const float* inputs = (const float*)d_in[0];   // [64,32,32,64] fp32
    const float* weight = (const float*)d_in[1];   // [1024,64] fp32
    float* out = (float*)d_out;

    cudaFuncSetAttribute(k_main, cudaFuncAttributeMaxDynamicSharedMemorySize, SM_TOTAL);
    k_prep<<<8, 128>>>(weight);
    k_main<<<N_TOKENS / BM, NTHR, SM_TOTAL>>>(inputs, weight, out);
}

// round 8
// speedup vs baseline: 1.4415x; 1.3903x over previous
#include <cuda_runtime.h>
#include <cuda_bf16.h>
#include <cstdint>

// Problem constants
#define NUM_EMB   1024
#define DIM       64
#define N_TOKENS  65536
#define BM        128          // tokens per CTA
#define BN        128          // codes per chunk
#define NCH       8            // 1024/128
#define PAD       68
#define NTHR      256          // 8 warps

// Output layout (single fp32 buffer)
#define OFF_Q     1
#define OFF_PPL   (1 + N_TOKENS*DIM)
#define OFF_IDX   (2 + N_TOKENS*DIM)

typedef unsigned long long ull;

// Device state
__device__ __nv_bfloat16 g_wsp[NUM_EMB * 128];  // per code: [e1(64) | e2(64)]
__device__ float    g_ensq[NUM_EMB];
__device__ float    g_counts[NUM_EMB];
__device__ float    g_loss_sum;
__device__ unsigned g_ticket;

// ---------------------------------------------------------------------------
// smem layout (bytes)
#define SM_AB     0                        // bf16 [x1|x2]: 128*256 = 32768
#define SM_B      32768                    // 2 bufs * 128*256 = 65536
#define SM_EN     98304                    // 1024 floats (biased +1) = 4096
#define SM_XSQ    102400                   // 128 floats -> 512
#define SM_IDX    102912                   // 128 ints -> 512
#define SM_PART   103424                   // 256 floats = 1024
#define SM_TICK   104448
#define SM_TOTAL  104464

// ---------------------------------------------------------------------------
#define LDSM_X4(r0,r1,r2,r3,addr) \
  asm volatile("ldmatrix.sync.aligned.m8n8.x4.shared.b16 {%0,%1,%2,%3}, [%4];" \
    : "=r"(r0),"=r"(r1),"=r"(r2),"=r"(r3) : "r"(addr))

#define MMA16816(d,a,b0,b1) \
  asm volatile("mma.sync.aligned.m16n8k16.row.col.f32.bf16.bf16.f32 " \
    "{%0,%1,%2,%3},{%4,%5,%6,%7},{%8,%9},{%0,%1,%2,%3};" \
    : "+f"((d)[0]),"+f"((d)[1]),"+f"((d)[2]),"+f"((d)[3]) \
    : "r"((a)[0]),"r"((a)[1]),"r"((a)[2]),"r"((a)[3]),"r"(b0),"r"(b1))

__device__ __forceinline__ void cp16(unsigned saddr, const void* gaddr) {
    asm volatile("cp.async.cg.shared.global [%0], [%1], 16;" :: "r"(saddr), "l"(gaddr));
}
#define CP_COMMIT() asm volatile("cp.async.commit_group;" ::: "memory")
#define CP_WAIT1()  asm volatile("cp.async.wait_group 1;" ::: "memory")
#define CP_WAIT0()  asm volatile("cp.async.wait_group 0;" ::: "memory")
__device__ __forceinline__ float ldcg(const float* p) {
    float v; asm volatile("ld.global.cg.f32 %0, [%1];" : "=f"(v) : "l"(p)); return v;
}

// top-3 key insert (smaller key = better (metric, idx))
__device__ __forceinline__ void ins3(ull& t0, ull& t1, ull& t2, ull k) {
    if (k < t2) {
        if (k < t0)      { t2 = t1; t1 = t0; t0 = k; }
        else if (k < t1) { t2 = t1; t1 = k; }
        else               t2 = k;
    }
}
__device__ __forceinline__ ull mkkey(float s, int idx) {
    return ((ull)__float_as_uint(s) << 10) | (unsigned)idx;
}
__device__ __forceinline__ float keysc(ull k) {
    return __uint_as_float((unsigned)(k >> 10));
}

// ---------------------------------------------------------------------------
// k_prep: W exact 2-way bf16 split + code norms (sequential unfused = ref)
// ---------------------------------------------------------------------------
__global__ void k_prep(const float* __restrict__ weight) {
    __shared__ float sw[128 * PAD];
    const int tid = threadIdx.x;             // 128
    const int b   = blockIdx.x;              // 8
    const float* g = weight + (size_t)b * 128 * DIM;
#pragma unroll
    for (int i = 0; i < 64; ++i) {
        int e = tid + i * 128;
        sw[(e >> 6) * PAD + (e & 63)] = g[e];
    }
    __syncthreads();
    const int k = b * 128 + tid;
    const float* x = sw + tid * PAD;
    float s = 0.f;
#pragma unroll
    for (int d = 0; d < DIM; ++d) {
        float v = x[d];
        s = __fadd_rn(s, __fmul_rn(v, v));
        __nv_bfloat16 e1 = __float2bfloat16_rn(v);
        float r1 = v - __bfloat162float(e1);
        __nv_bfloat16 e2 = __float2bfloat16_rn(r1);
        g_wsp[(size_t)k * 128 + d]      = e1;
        g_wsp[(size_t)k * 128 + 64 + d] = e2;
    }
    g_ensq[k] = s;
}

// ---------------------------------------------------------------------------
// k_main: 3-term bf16-split mma.sync pruning GEMM + exact-rescore argmin
// ---------------------------------------------------------------------------
__global__ __launch_bounds__(NTHR, 2)
void k_main(const float* __restrict__ inputs,
            const float* __restrict__ weight,
            float* __restrict__ out) {
    extern __shared__ char smem[];
    float* s_en  = (float*)(smem + SM_EN);    // 1 + ensq (biased)
    float* s_xsq = (float*)(smem + SM_XSQ);
    int*   s_idx = (int*)  (smem + SM_IDX);
    float* s_part= (float*)(smem + SM_PART);
    unsigned* s_tick = (unsigned*)(smem + SM_TICK);

    const uint32_t sbase = (uint32_t)__cvta_generic_to_shared(smem);
    const int tid  = threadIdx.x;
    const int w    = tid >> 5;
    const int lane = tid & 31;
    const int tok0 = blockIdx.x * BM;

    // --- prefetch B chunk 0: [e1|e2] rows (256B), SW swizzled ---
#pragma unroll
    for (int it = 0; it < 8; ++it) {
        int e = tid + it * NTHR;             // 0..2047
        int row = e >> 4, g = e & 15;
        uint32_t dst = sbase + SM_B + row * 256 + ((g >> 3) << 7)
                     + ((((g & 7) ^ (row & 7)) << 4));
        cp16(dst, g_wsp + ((size_t)row << 7) + g * 8);
    }
    CP_COMMIT();

    // --- biased code norms (1 + ensq): approx metric bias keeps bits monotone
#pragma unroll
    for (int it = 0; it < 4; ++it) {
        int e = tid + it * NTHR;
        s_en[e] = 1.0f + g_ensq[e];
    }

    // --- A exact 2-way bf16 split straight from gmem (coalesced) ---
    {
        const float* gx = inputs + (size_t)tok0 * DIM;
#pragma unroll
        for (int it = 0; it < 32; ++it) {
            int e = tid + it * NTHR;         // 0..8191
            int row = e >> 6, d = e & 63;
            float v = __ldg(gx + e);
            __nv_bfloat16 x1 = __float2bfloat16_rn(v);
            float r1 = v - __bfloat162float(x1);
            __nv_bfloat16 x2 = __float2bfloat16_rn(r1);
            uint32_t sw = (uint32_t)((((d >> 3) & 7) ^ (row & 7)) << 4)
                        | (uint32_t)((d * 2) & 15);
            *(__nv_bfloat16*)(smem + SM_AB + row * 256 + sw)       = x1;
            *(__nv_bfloat16*)(smem + SM_AB + row * 256 + 128 + sw) = x2;
        }
    }

    // --- ||x||^2: sequential UNFUSED (replicates reference rounding) ---
    if (tid < BM) {
        const float* x = inputs + (size_t)(tok0 + tid) * DIM;
        float s = 0.f;
#pragma unroll
        for (int d = 0; d < DIM; ++d) {
            float v = __ldg(x + d);
            s = __fadd_rn(s, __fmul_rn(v, v));
        }
        s_xsq[tid] = s;
    }
    __syncthreads();

    // --- per-warp A fragments in registers: m16 x k128 ([x1|x2]) ---
    uint32_t afr[8][4];
    {
        const int tr = lane & 15;
        const int kadd = (lane >> 4) * 16;
#pragma unroll
        for (int u = 0; u < 8; ++u) {
            int kb = u * 32 + kadd;
            uint32_t addr = sbase + SM_AB + (w * 16 + tr) * 256 + (kb & 128)
                          + (((((kb >> 4) & 7) ^ (tr & 7)) << 4));
            LDSM_X4(afr[u][0], afr[u][1], afr[u][2], afr[u][3], addr);
        }
    }

    // --- B lane address offsets (i=0,1 -> e1; i=2,3 -> e2) ---
    const int cr = lane & 7;
    const int klane = (lane >> 3) & 3;
    uint32_t boff[4];
#pragma unroll
    for (int i = 0; i < 4; ++i) {
        int kb = i * 64 + klane * 16;
        boff[i] = (uint32_t)(cr * 256 + (kb & 128)
                + (((((kb >> 4) & 7) ^ cr) << 4)));
    }

    const float xq_lo = s_xsq[w * 16 + (lane >> 2)];
    const float xq_hi = s_xsq[w * 16 + (lane >> 2) + 8];
    ull kLo0 = ~0ull, kLo1 = ~0ull, kLo2 = ~0ull;
    ull kHi0 = ~0ull, kHi1 = ~0ull, kHi2 = ~0ull;

    for (int c = 0; c < NCH; ++c) {
        if (c + 1 < NCH) {
            const uint32_t dst0 = sbase + SM_B + ((c + 1) & 1) * 32768;
            const size_t srow = (size_t)(c + 1) * BN;
#pragma unroll
            for (int it = 0; it < 8; ++it) {
                int e = tid + it * NTHR;
                int row = e >> 4, g = e & 15;
                uint32_t dst = dst0 + row * 256 + ((g >> 3) << 7)
                             + ((((g & 7) ^ (row & 7)) << 4));
                cp16(dst, g_wsp + ((srow + row) << 7) + g * 8);
            }
            CP_COMMIT();
            CP_WAIT1();
        } else {
            CP_COMMIT();
            CP_WAIT0();
        }
        __syncthreads();

        const uint32_t bbuf = sbase + SM_B + (c & 1) * 32768;

#pragma unroll 1
        for (int s8 = 0; s8 < 8; ++s8) {
            const int n0a = s8 * 16;
            const int n0b = n0a + 8;
            // 6 independent accumulator chains (3 phases x 2 columns)
            float d1A[4] = {0,0,0,0}, d2A[4] = {0,0,0,0}, d3A[4] = {0,0,0,0};
            float d1B[4] = {0,0,0,0}, d2B[4] = {0,0,0,0}, d3B[4] = {0,0,0,0};
            uint32_t fa[8], fb[8];

            // ---- e1 fragments -> x1.e1 (d1), x2.e1 (d3) ----
            LDSM_X4(fa[0],fa[1],fa[2],fa[3], bbuf + n0a * 256 + boff[0]);
            LDSM_X4(fa[4],fa[5],fa[6],fa[7], bbuf + n0a * 256 + boff[1]);
            LDSM_X4(fb[0],fb[1],fb[2],fb[3], bbuf + n0b * 256 + boff[0]);
            LDSM_X4(fb[4],fb[5],fb[6],fb[7], bbuf + n0b * 256 + boff[1]);
#pragma unroll
            for (int j = 0; j < 4; ++j) {
                MMA16816(d1A, afr[j],   fa[2*j], fa[2*j+1]);
                MMA16816(d1B, afr[j],   fb[2*j], fb[2*j+1]);
                MMA16816(d3A, afr[4+j], fa[2*j], fa[2*j+1]);
                MMA16816(d3B, afr[4+j], fb[2*j], fb[2*j+1]);
            }
            // ---- e2 fragments -> x1.e2 (d2) ----
            LDSM_X4(fa[0],fa[1],fa[2],fa[3], bbuf + n0a * 256 + boff[2]);
            LDSM_X4(fa[4],fa[5],fa[6],fa[7], bbuf + n0a * 256 + boff[3]);
            LDSM_X4(fb[0],fb[1],fb[2],fb[3], bbuf + n0b * 256 + boff[2]);
            LDSM_X4(fb[4],fb[5],fb[6],fb[7], bbuf + n0b * 256 + boff[3]);
#pragma unroll
            for (int j = 0; j < 4; ++j) {
                MMA16816(d2A, afr[j],   fa[2*j], fa[2*j+1]);
                MMA16816(d2B, afr[j],   fb[2*j], fb[2*j+1]);
            }

            // approx metric m = fl((1+ensq) - 2*dot); track top-3 keys
            {
                int col = c * BN + n0a + (lane & 3) * 2;
                float en0 = s_en[col], en1 = s_en[col + 1];
                float q0 = (d1A[0] + d2A[0]) + d3A[0];
                float q1 = (d1A[1] + d2A[1]) + d3A[1];
                float q2 = (d1A[2] + d2A[2]) + d3A[2];
                float q3 = (d1A[3] + d2A[3]) + d3A[3];
                ins3(kLo0,kLo1,kLo2, mkkey(fmaf(-2.f, q0, en0), col));
                ins3(kLo0,kLo1,kLo2, mkkey(fmaf(-2.f, q1, en1), col + 1));
                ins3(kHi0,kHi1,kHi2, mkkey(fmaf(-2.f, q2, en0), col));
                ins3(kHi0,kHi1,kHi2, mkkey(fmaf(-2.f, q3, en1), col + 1));
            }
            {
                int col = c * BN + n0b + (lane & 3) * 2;
                float en0 = s_en[col], en1 = s_en[col + 1];
                float q0 = (d1B[0] + d2B[0]) + d3B[0];
                float q1 = (d1B[1] + d2B[1]) + d3B[1];
                float q2 = (d1B[2] + d2B[2]) + d3B[2];
                float q3 = (d1B[3] + d2B[3]) + d3B[3];
                ins3(kLo0,kLo1,kLo2, mkkey(fmaf(-2.f, q0, en0), col));
                ins3(kLo0,kLo1,kLo2, mkkey(fmaf(-2.f, q1, en1), col + 1));
                ins3(kHi0,kHi1,kHi2, mkkey(fmaf(-2.f, q2, en0), col));
                ins3(kHi0,kHi1,kHi2, mkkey(fmaf(-2.f, q3, en1), col + 1));
            }
        }
        __syncthreads();
    }

    // --- winner resolution: window filter + exact (round-1) rescore ---
#pragma unroll
    for (int half = 0; half < 2; ++half) {
        ull k0 = half ? kHi0 : kLo0;
        ull k1 = half ? kHi1 : kLo1;
        ull k2 = half ? kHi2 : kLo2;
        float xq = half ? xq_hi : xq_lo;
        int trow = w * 16 + (lane >> 2) + half * 8;

        ull m = k0, o;
        o = __shfl_xor_sync(0xffffffffu, m, 1); m = o < m ? o : m;
        o = __shfl_xor_sync(0xffffffffu, m, 2); m = o < m ? o : m;
        float win = keysc(m) + 2e-5f;

        float s0f = keysc(k0), s1f = keysc(k1), s2f = keysc(k2);
        int cnt = (int)(s0f <= win) + (int)(s1f <= win) + (int)(s2f <= win);
        cnt += __shfl_xor_sync(0xffffffffu, cnt, 1);
        cnt += __shfl_xor_sync(0xffffffffu, cnt, 2);

        ull ebest = ~0ull;
        if (cnt > 1) {
            const float* xrow = inputs + (size_t)(tok0 + trow) * DIM;
            ull   ks[3] = {k0, k1, k2};
            float sf[3] = {s0f, s1f, s2f};
#pragma unroll 1
            for (int j = 0; j < 3; ++j) {
                if (sf[j] <= win) {
                    int idx = (int)(ks[j] & 1023);
                    const float* wrow = weight + (size_t)idx * DIM;
                    float aLo = 0.f, aHi = 0.f;
#pragma unroll
                    for (int d = 0; d < 32; ++d) {
                        aLo = fmaf(__ldg(xrow + 2*d),     __ldg(wrow + 2*d),     aLo);
                        aHi = fmaf(__ldg(xrow + 2*d + 1), __ldg(wrow + 2*d + 1), aHi);
                    }
                    float dot = __fadd_rn(aLo, aHi);
                    float es = fmaf(-2.f, dot, __fadd_rn(xq, ldcg(&g_ensq[idx])));
                    ull ek = mkkey(es, idx);
                    if (ek < ebest) ebest = ek;
                }
            }
        }
        o = __shfl_xor_sync(0xffffffffu, ebest, 1); ebest = o < ebest ? o : ebest;
        o = __shfl_xor_sync(0xffffffffu, ebest, 2); ebest = o < ebest ? o : ebest;

        int widx = (cnt == 1) ? (int)(m & 1023) : (int)(ebest & 1023);
        if ((lane & 3) == 0) {
            s_idx[trow] = widx;
            out[OFF_IDX + (size_t)(tok0 + trow)] = (float)widx;
            atomicAdd(&g_counts[widx], 1.f);
        }
    }
    __syncthreads();

    // --- gather codes -> quantized output + loss partial ---
    float local = 0.f;
    {
        const float* gx = inputs + (size_t)tok0 * DIM;
#pragma unroll
        for (int it = 0; it < 32; ++it) {
            int e = tid + it * NTHR;         // 0..8191
            int t = e >> 6, d = e & 63;
            float q = weight[(size_t)s_idx[t] * DIM + d];
            float x = __ldg(gx + e);
            out[OFF_Q + (size_t)(tok0 + t) * DIM + d] = q;
            float diff = q - x;
            local = fmaf(diff, diff, local);
        }
    }
    s_part[tid] = local;
    __syncthreads();
    for (int off = 128; off > 0; off >>= 1) {
        if (tid < off) s_part[tid] += s_part[tid + off];
        __syncthreads();
    }
    if (tid == 0) atomicAdd(&g_loss_sum, s_part[0]);

    // --- last-block finalization (ticket) ---
    __threadfence();
    if (tid == 0) *s_tick = atomicAdd(&g_ticket, 1u);
    __syncthreads();
    if (*s_tick == (unsigned)(gridDim.x - 1)) {
        float acc_pl = 0.f;
#pragma unroll
        for (int rj = 0; rj < 4; ++rj) {
            float cnt = ldcg(&g_counts[tid + rj * NTHR]);
            float p = cnt * (1.f / 65536.f);
            acc_pl += p * logf(p + 1e-10f);
        }
        s_part[tid] = acc_pl;
        __syncthreads();
        for (int off = 128; off > 0; off >>= 1) {
            if (tid < off) s_part[tid] += s_part[tid + off];
            __syncthreads();
        }
        if (tid == 0) {
            float ls = ldcg(&g_loss_sum);
            out[0]       = 1.25f * ls * (1.f / (float)(N_TOKENS * DIM));
            out[OFF_PPL] = expf(-s_part[0]);
            g_loss_sum = 0.f;
            g_ticket   = 0u;
        }
#pragma unroll
        for (int rj = 0; rj < 4; ++rj) g_counts[tid + rj * NTHR] = 0.f;
    }
}

// ---------------------------------------------------------------------------
extern "C" void kernel_launch(void* const* d_in, const int* in_sizes, int n_in,
                              void* d_out, int out_size) {
    const float* inputs = (const float*)d_in[0];   // [64,32,32,64] fp32
    const float* weight = (const float*)d_in[1];   // [1024,64] fp32
    float* out = (float*)d_out;

    cudaFuncSetAttribute(k_main, cudaFuncAttributeMaxDynamicSharedMemorySize, SM_TOTAL);
    k_prep<<<8, 128>>>(weight);
    k_main<<<N_TOKENS / BM, NTHR, SM_TOTAL>>>(inputs, weight, out);
}